// round 14
// baseline (speedup 1.0000x reference)
#include <cuda_runtime.h>
#include <cuda_bf16.h>
#include <mma.h>
#include <math.h>
#include <stdint.h>
#include <cstdint>

using namespace nvcuda;

// ---------------- problem constants ----------------
#define BB 8
#define TT 2048
#define DD 1024
#define NN 32768
#define KSEL 64
#define HH 16
#define DH 64
#define LN_EPS 1e-5f

#define BT (BB*TT)          // 16384
#define BTD (BB*TT*DD)      // 16777216
#define DD2 (DD*DD)         // 1048576

// ---------------- device scratch ----------------
__device__ __nv_bfloat16 g_hnorm[BTD];
__device__ float g_mu[BT];
__device__ float g_rstd[BT];
__device__ float g_hsumraw[BB*DD];
__device__ float g_fq[BB*DD];
__device__ float g_sel[BB*NN];
__device__ int   g_topk[BB*KSEL];
__device__ __nv_bfloat16 g_kvbf[2*BB*KSEL*DD];  // k then v (bf16)
__device__ __nv_bfloat16 g_qbf[BTD];            // q bf16
__device__ __nv_bfloat16 g_attnout[BTD];
__device__ float g_attnsum[BB*KSEL];
__device__ __nv_bfloat16 g_wbf[4*DD2];          // qw, kw, vw, ow bf16

// ---------------- weight conversion + zeroing (fused) ----------------
__global__ void convw_zero_kernel(const float* __restrict__ qw, const float* __restrict__ kw,
                                  const float* __restrict__ vw, const float* __restrict__ ow,
                                  float* __restrict__ dout) {
    int g = blockIdx.x*256 + threadIdx.x;
    if (g < BB*NN) dout[BTD + g] = 0.f;
    if (g < BB*DD) { g_hsumraw[g] = 0.f; g_fq[g] = 0.f; }
    if (g < BB*KSEL) g_attnsum[g] = 0.f;
    for (int i = g; i < DD2; i += 2048*256) {
        g_wbf[i]         = __float2bfloat16(qw[i]);
        g_wbf[DD2 + i]   = __float2bfloat16(kw[i]);
        g_wbf[2*DD2 + i] = __float2bfloat16(vw[i]);
        g_wbf[3*DD2 + i] = __float2bfloat16(ow[i]);
    }
}

// ---------------- LayerNorm -> bf16 h_norm ----------------
__global__ __launch_bounds__(256) void ln_kernel(const float* __restrict__ h,
                                                 const float* __restrict__ lg,
                                                 const float* __restrict__ lb) {
    int row = blockIdx.x;
    int tid = threadIdx.x;
    const float4* x4 = (const float4*)(h + (size_t)row*DD);
    float4 v = x4[tid];
    float s  = v.x + v.y + v.z + v.w;
    float s2 = v.x*v.x + v.y*v.y + v.z*v.z + v.w*v.w;
    #pragma unroll
    for (int o = 16; o; o >>= 1) {
        s  += __shfl_xor_sync(0xffffffffu, s, o);
        s2 += __shfl_xor_sync(0xffffffffu, s2, o);
    }
    __shared__ float ws[8], ws2[8];
    __shared__ float smu, srstd;
    if ((tid & 31) == 0) { ws[tid>>5] = s; ws2[tid>>5] = s2; }
    __syncthreads();
    if (tid == 0) {
        float ts = 0.f, ts2 = 0.f;
        #pragma unroll
        for (int i = 0; i < 8; i++) { ts += ws[i]; ts2 += ws2[i]; }
        float mu = ts / DD;
        float var = ts2 / DD - mu*mu;
        float rstd = rsqrtf(var + LN_EPS);
        smu = mu; srstd = rstd;
        g_mu[row] = mu; g_rstd[row] = rstd;
    }
    __syncthreads();
    float mu = smu, rstd = srstd;
    const float4* g4 = (const float4*)lg;
    const float4* b4 = (const float4*)lb;
    float4 gg = g4[tid], bb = b4[tid];
    __nv_bfloat16* out = g_hnorm + (size_t)row*DD + tid*4;
    out[0] = __float2bfloat16((v.x - mu)*rstd*gg.x + bb.x);
    out[1] = __float2bfloat16((v.y - mu)*rstd*gg.y + bb.y);
    out[2] = __float2bfloat16((v.z - mu)*rstd*gg.z + bb.z);
    out[3] = __float2bfloat16((v.w - mu)*rstd*gg.w + bb.w);
}

// ---------------- column sums of normalized h (fp32 path), strided ----------------
__global__ __launch_bounds__(256) void hsum_kernel(const float* __restrict__ h) {
    int b = blockIdx.x;
    int j = blockIdx.y*256 + threadIdx.x;
    int t0 = blockIdx.z*64;
    float a0=0.f, a1=0.f, a2=0.f, a3=0.f;
    for (int t = t0; t < t0 + 64; t += 4) {
        int r = b*TT + t;
        a0 += (h[(size_t)r*DD + j]     - g_mu[r])   * g_rstd[r];
        a1 += (h[(size_t)(r+1)*DD + j] - g_mu[r+1]) * g_rstd[r+1];
        a2 += (h[(size_t)(r+2)*DD + j] - g_mu[r+2]) * g_rstd[r+2];
        a3 += (h[(size_t)(r+3)*DD + j] - g_mu[r+3]) * g_rstd[r+3];
    }
    atomicAdd(&g_hsumraw[b*DD + j], (a0+a1)+(a2+a3));
}

// ---------------- focus_query (fp32), split over K-slices ----------------
__global__ __launch_bounds__(256) void focus_kernel(const float* __restrict__ fw,
                                                    const float* __restrict__ fb,
                                                    const float* __restrict__ lg,
                                                    const float* __restrict__ lb) {
    int b = blockIdx.x;
    int z = blockIdx.y;
    int tid = threadIdx.x;
    __shared__ float hs[128];
    for (int i = tid; i < 128; i += 256) {
        int gi = z*128 + i;
        hs[i] = (g_hsumraw[b*DD + gi] * (1.f/TT)) * lg[gi] + lb[gi];
    }
    __syncthreads();
    float acc[4] = {0.f, 0.f, 0.f, 0.f};
    for (int i = 0; i < 128; i++) {
        float hv = hs[i];
        const float* fr = fw + (size_t)(z*128 + i)*DD + tid;
        acc[0] += hv * fr[0];
        acc[1] += hv * fr[256];
        acc[2] += hv * fr[512];
        acc[3] += hv * fr[768];
    }
    #pragma unroll
    for (int k = 0; k < 4; k++) {
        float v = acc[k];
        if (z == 0) v += fb[tid + k*256];
        atomicAdd(&g_fq[b*DD + tid + k*256], v);
    }
}

// ---------------- selection = fq @ memory^T + aw * activations ----------------
__global__ __launch_bounds__(256) void sel_kernel(const float* __restrict__ mem,
                                                  const float* __restrict__ act,
                                                  const float* __restrict__ awp) {
    __shared__ float fqs[BB][DD];
    int tid = threadIdx.x;
    for (int i = tid; i < BB*DD; i += 256)
        fqs[i >> 10][i & 1023] = g_fq[i];
    __syncthreads();
    int warp = tid >> 5, lane = tid & 31;
    int n = blockIdx.x*8 + warp;
    float acc[BB];
    #pragma unroll
    for (int b = 0; b < BB; b++) acc[b] = 0.f;
    const float* mrow = mem + (size_t)n*DD;
    for (int i = lane; i < DD; i += 32) {
        float m = mrow[i];
        #pragma unroll
        for (int b = 0; b < BB; b++) acc[b] += m * fqs[b][i];
    }
    #pragma unroll
    for (int b = 0; b < BB; b++) {
        float a = acc[b];
        #pragma unroll
        for (int o = 16; o; o >>= 1) a += __shfl_xor_sync(0xffffffffu, a, o);
        if (lane == 0) g_sel[b*NN + n] = a + awp[0] * act[b*NN + n];
    }
}

// ---------------- exact top-64 via MSB-first radix select (parallel scans) ----------------
__device__ __forceinline__ unsigned fkey(float f) {
    unsigned u = __float_as_uint(f);
    return (u & 0x80000000u) ? ~u : (u | 0x80000000u);
}

__global__ __launch_bounds__(1024) void topk_kernel() {
    int b = blockIdx.x;
    int tid = threadIdx.x;
    __shared__ unsigned hist[256];
    __shared__ unsigned suf[256];
    __shared__ unsigned s_prefix;
    __shared__ int s_remaining;
    __shared__ unsigned s_gt, s_eq;
    __shared__ int eqidx[256];
    const float* sel = g_sel + b*NN;
    unsigned prefix = 0;
    int remaining = KSEL;
    for (int shift = 24; shift >= 0; shift -= 8) {
        if (tid < 256) hist[tid] = 0;
        __syncthreads();
        for (int i = tid; i < NN; i += 1024) {
            unsigned k = fkey(sel[i]);
            bool match = (shift == 24) || ((k >> (shift+8)) == (prefix >> (shift+8)));
            if (match) atomicAdd(&hist[(k >> shift) & 255], 1u);
        }
        __syncthreads();
        // parallel suffix sum: suf[i] = sum_{k>=i} hist[k]
        if (tid < 256) suf[tid] = hist[tid];
        __syncthreads();
        #pragma unroll
        for (int off = 1; off < 256; off <<= 1) {
            unsigned v = 0;
            if (tid < 256) {
                v = suf[tid];
                if (tid + off < 256) v += suf[tid + off];
            }
            __syncthreads();
            if (tid < 256) suf[tid] = v;
            __syncthreads();
        }
        // bucket = max j with suf[j] >= remaining
        if (tid < 256) {
            unsigned here = suf[tid];
            unsigned nxt = (tid == 255) ? 0u : suf[tid + 1];
            if (here >= (unsigned)remaining && nxt < (unsigned)remaining) {
                s_prefix = prefix | ((unsigned)tid << shift);
                s_remaining = remaining - (int)nxt;
            }
        }
        __syncthreads();
        prefix = s_prefix;
        remaining = s_remaining;
        __syncthreads();
    }
    if (tid == 0) { s_gt = 0; s_eq = 0; }
    __syncthreads();
    int* out = g_topk + b*KSEL;
    for (int i = tid; i < NN; i += 1024) {
        unsigned k = fkey(sel[i]);
        if (k > prefix) {
            out[atomicAdd(&s_gt, 1u)] = i;
        } else if (k == prefix) {
            unsigned p = atomicAdd(&s_eq, 1u);
            if (p < 256) eqidx[p] = i;
        }
    }
    __syncthreads();
    if (tid == 0) {
        int cnt = min((int)s_eq, 256);
        int base = (int)s_gt;
        for (int r = 0; r < remaining; r++) {
            int mi = 0;
            for (int i2 = 1; i2 < cnt; i2++)
                if (eqidx[i2] < eqidx[mi]) mi = i2;
            out[base + r] = eqidx[mi];
            eqidx[mi] = 0x7fffffff;
        }
    }
}

// ---------------- mma.sync helpers ----------------
__device__ __forceinline__ void ldsm_x4(uint32_t& r0, uint32_t& r1, uint32_t& r2, uint32_t& r3,
                                        uint32_t addr) {
    asm volatile("ldmatrix.sync.aligned.m8n8.x4.shared.b16 {%0,%1,%2,%3}, [%4];"
                 : "=r"(r0), "=r"(r1), "=r"(r2), "=r"(r3) : "r"(addr));
}
__device__ __forceinline__ void ldsm_x4_t(uint32_t& r0, uint32_t& r1, uint32_t& r2, uint32_t& r3,
                                          uint32_t addr) {
    asm volatile("ldmatrix.sync.aligned.m8n8.x4.trans.shared.b16 {%0,%1,%2,%3}, [%4];"
                 : "=r"(r0), "=r"(r1), "=r"(r2), "=r"(r3) : "r"(addr));
}
__device__ __forceinline__ void mma16816(float* c, const uint32_t* a, const uint32_t* b) {
    asm volatile("mma.sync.aligned.m16n8k16.row.col.f32.bf16.bf16.f32 "
                 "{%0,%1,%2,%3}, {%4,%5,%6,%7}, {%8,%9}, {%0,%1,%2,%3};"
                 : "+f"(c[0]), "+f"(c[1]), "+f"(c[2]), "+f"(c[3])
                 : "r"(a[0]), "r"(a[1]), "r"(a[2]), "r"(a[3]), "r"(b[0]), "r"(b[1]));
}

// ---------------- 3-stage cp.async hand-MMA GEMM ----------------
// EPI 0: bf16 out = A@B + bias (q)
// EPI 1: fp32 out = h + gate*(A@B + bias)  (o-proj + residual)
// EPI 2: bf16 out, A gathered inline from fp32 memory via g_topk; z picks weight/bias/dst
#define STG 3
#define BMG 128
#define BNG 128
#define BKG 64
#define NTHR 128
#define ALD (BKG+8)      // 72 bf16 (144B rows)
#define BLD (BNG+8)      // 136 bf16 (272B rows)
#define CLD 68           // epilogue fp32 staging stride (272B, conflict-free)
#define SMEM_GEMM (STG*(BMG*ALD + BKG*BLD)*2 + BNG*4 + BMG*4)   // + topk idx cache

template<int EPI>
__global__ __launch_bounds__(NTHR, 2) void gemm_bf16(
    const __nv_bfloat16* __restrict__ A,
    const __nv_bfloat16* __restrict__ Bm,
    const float* __restrict__ bias,
    const float* __restrict__ bias2,
    void* __restrict__ Cout,
    const float* __restrict__ hres,
    const float* __restrict__ glp,
    const float* __restrict__ memsrc,
    int M, int N, int K)
{
    extern __shared__ char smraw[];
    __nv_bfloat16* As = (__nv_bfloat16*)smraw;               // 3 x 128x72
    __nv_bfloat16* Bs = As + STG*BMG*ALD;                    // 3 x 64x136
    float* biasT = (float*)(Bs + STG*BKG*BLD);               // 128
    int* tks = (int*)(biasT + BNG);                          // 128 (EPI2 gather indices)

    int tid = threadIdx.x;
    int warp = tid >> 5, lane = tid & 31;
    int wm = warp >> 1;
    int wn = warp & 1;
    int rowBase = blockIdx.y * BMG;
    int colBase = blockIdx.x * BNG;

    const __nv_bfloat16* Bp = Bm;
    const float* bp = bias;
    size_t dstOff = 0;
    if (EPI == 2) {
        int z = blockIdx.z;
        Bp = Bm + (size_t)z * DD2;
        dstOff = (size_t)z * (BB*KSEL*DD);
        bp = z ? bias2 : bias;
    }

    if (tid < BNG) biasT[tid] = bp[colBase + tid];
    if (EPI == 2 && tid < BMG) tks[tid] = g_topk[rowBase + tid];
    __syncthreads();

    float acc[4][8][4];
    {
        int cb = wn*64 + (lane & 3)*2;
        #pragma unroll
        for (int ni = 0; ni < 8; ni++) {
            float b0 = biasT[cb + ni*8];
            float b1 = biasT[cb + ni*8 + 1];
            #pragma unroll
            for (int mi = 0; mi < 4; mi++) {
                acc[mi][ni][0] = b0; acc[mi][ni][1] = b1;
                acc[mi][ni][2] = b0; acc[mi][ni][3] = b1;
            }
        }
    }

    auto load_stage = [&](int s, int k0) {
        if (EPI == 2) {
            // gather A rows from fp32 memory via topk indices, convert to bf16 in-flight
            #pragma unroll
            for (int c = 0; c < 8; c++) {
                int lin = tid + c*NTHR;
                int ar = lin >> 3, ac = (lin & 7)*8;
                const float4* src = (const float4*)(memsrc + (size_t)tks[ar]*DD + k0 + ac);
                float4 v0 = src[0], v1 = src[1];
                __nv_bfloat162 p0 = __float22bfloat162_rn(make_float2(v0.x, v0.y));
                __nv_bfloat162 p1 = __float22bfloat162_rn(make_float2(v0.z, v0.w));
                __nv_bfloat162 p2 = __float22bfloat162_rn(make_float2(v1.x, v1.y));
                __nv_bfloat162 p3 = __float22bfloat162_rn(make_float2(v1.z, v1.w));
                uint4 pk;
                pk.x = *(unsigned*)&p0; pk.y = *(unsigned*)&p1;
                pk.z = *(unsigned*)&p2; pk.w = *(unsigned*)&p3;
                *(uint4*)(As + s*BMG*ALD + ar*ALD + ac) = pk;
            }
        } else {
            #pragma unroll
            for (int c = 0; c < 8; c++) {
                int lin = tid + c*NTHR;
                int ar = lin >> 3, ac = (lin & 7)*8;
                unsigned da = (unsigned)__cvta_generic_to_shared(As + s*BMG*ALD + ar*ALD + ac);
                const void* ga = A + (size_t)(rowBase+ar)*K + k0 + ac;
                asm volatile("cp.async.cg.shared.global [%0], [%1], 16;\n" :: "r"(da), "l"(ga));
            }
        }
        #pragma unroll
        for (int c = 0; c < 8; c++) {
            int lin = tid + c*NTHR;
            int br = lin >> 4, bc = (lin & 15)*8;
            unsigned db = (unsigned)__cvta_generic_to_shared(Bs + s*BKG*BLD + br*BLD + bc);
            const void* gb = Bp + (size_t)(k0+br)*N + colBase + bc;
            asm volatile("cp.async.cg.shared.global [%0], [%1], 16;\n" :: "r"(db), "l"(gb));
        }
        asm volatile("cp.async.commit_group;\n");
    };

    int NK = K / BKG;
    load_stage(0, 0);
    load_stage(1, BKG);

    int arow = lane & 15;
    int acol8 = (lane >> 4) * 8;

    for (int i = 0; i < NK; i++) {
        asm volatile("cp.async.wait_group %0;\n" :: "n"(STG-2));
        __syncthreads();
        if (i + STG - 1 < NK) load_stage((i + STG - 1) % STG, (i + STG - 1) * BKG);
        else asm volatile("cp.async.commit_group;\n");
        int buf = i % STG;
        const __nv_bfloat16* Ab = As + buf*BMG*ALD + (wm*64 + arow)*ALD + acol8;
        const __nv_bfloat16* Bb = Bs + buf*BKG*BLD + arow*BLD + wn*64 + acol8;
        #pragma unroll
        for (int kk = 0; kk < BKG; kk += 16) {
            uint32_t af[4][4];
            #pragma unroll
            for (int mi = 0; mi < 4; mi++) {
                uint32_t aaddr = (uint32_t)__cvta_generic_to_shared(Ab + mi*16*ALD + kk);
                ldsm_x4(af[mi][0], af[mi][1], af[mi][2], af[mi][3], aaddr);
            }
            uint32_t bf[4][4];
            #pragma unroll
            for (int nj = 0; nj < 4; nj++) {
                uint32_t baddr = (uint32_t)__cvta_generic_to_shared(Bb + kk*BLD + nj*16);
                ldsm_x4_t(bf[nj][0], bf[nj][1], bf[nj][2], bf[nj][3], baddr);
            }
            #pragma unroll
            for (int mi = 0; mi < 4; mi++)
                #pragma unroll
                for (int nj = 0; nj < 4; nj++) {
                    mma16816(acc[mi][nj*2],     af[mi], &bf[nj][0]);
                    mma16816(acc[mi][nj*2 + 1], af[mi], &bf[nj][2]);
                }
        }
    }

    asm volatile("cp.async.wait_group 0;\n");
    __syncthreads();
    float* Cs = (float*)smraw + warp*(64*CLD);
    {
        int r0 = lane >> 2;
        int c0 = (lane & 3)*2;
        #pragma unroll
        for (int mi = 0; mi < 4; mi++)
            #pragma unroll
            for (int ni = 0; ni < 8; ni++) {
                float* dst = Cs + (mi*16 + r0)*CLD + ni*8 + c0;
                *(float2*)dst            = make_float2(acc[mi][ni][0], acc[mi][ni][1]);
                *(float2*)(dst + 8*CLD)  = make_float2(acc[mi][ni][2], acc[mi][ni][3]);
            }
    }
    __syncwarp();

    int row0 = rowBase + wm*64;
    int col0 = colBase + wn*64;

    if (EPI == 1) {
        float* C = (float*)Cout;
        float gate = 1.f / (1.f + __expf(-glp[0]));
        for (int it = lane; it < 64*16; it += 32) {
            int r = it >> 4, c4 = (it & 15)*4;
            size_t gi = (size_t)(row0 + r)*N + col0 + c4;
            float4 hv = *(const float4*)(hres + gi);
            const float* src = Cs + r*CLD + c4;
            float4 o;
            o.x = hv.x + gate*src[0]; o.y = hv.y + gate*src[1];
            o.z = hv.z + gate*src[2]; o.w = hv.w + gate*src[3];
            *(float4*)(C + gi) = o;
        }
    } else {
        __nv_bfloat16* C = (__nv_bfloat16*)Cout + dstOff;
        for (int it = lane; it < 64*8; it += 32) {
            int r = it >> 3, c8 = (it & 7)*8;
            const float* src = Cs + r*CLD + c8;
            __nv_bfloat162 p0 = __float22bfloat162_rn(make_float2(src[0], src[1]));
            __nv_bfloat162 p1 = __float22bfloat162_rn(make_float2(src[2], src[3]));
            __nv_bfloat162 p2 = __float22bfloat162_rn(make_float2(src[4], src[5]));
            __nv_bfloat162 p3 = __float22bfloat162_rn(make_float2(src[6], src[7]));
            uint4 pk;
            pk.x = *(unsigned*)&p0; pk.y = *(unsigned*)&p1;
            pk.z = *(unsigned*)&p2; pk.w = *(unsigned*)&p3;
            *(uint4*)(C + (size_t)(row0 + r)*N + col0 + c8) = pk;
        }
    }
}

// ---------------- tensor-core attention (WMMA) ----------------
#define QLD 72
#define SLD 72
#define SMEM_ATTN ((128*QLD + 64*QLD + 64*QLD)*2 + 128*SLD*4 + 128*QLD*2 + 64*4)

__global__ __launch_bounds__(256) void attn_kernel() {
    extern __shared__ char smc[];
    __nv_bfloat16* Qs = (__nv_bfloat16*)smc;
    __nv_bfloat16* Ks = Qs + 128*QLD;
    __nv_bfloat16* Vs = Ks + 64*QLD;
    float* Ss = (float*)(Vs + 64*QLD);
    __nv_bfloat16* Ps = (__nv_bfloat16*)(Ss + 128*SLD);
    float* colsum = (float*)(Ps + 128*QLD);

    int bh = blockIdx.x;
    int b = bh >> 4;
    int h = bh & 15;
    int t0 = blockIdx.y * 128;
    int tid = threadIdx.x;
    int warp = tid >> 5;

    if (tid < 64) colsum[tid] = 0.f;
    {
        const __nv_bfloat16* qsrc = g_qbf + (size_t)(b*TT + t0)*DD + h*DH;
        #pragma unroll
        for (int c = tid; c < 1024; c += 256) {
            int r = c >> 3, c8 = (c & 7)*8;
            *(uint4*)(Qs + r*QLD + c8) = *(const uint4*)(qsrc + (size_t)r*DD + c8);
        }
        const __nv_bfloat16* kbase = g_kvbf + (size_t)b*KSEL*DD + h*DH;
        const __nv_bfloat16* vbase = kbase + (size_t)BB*KSEL*DD;
        for (int c = tid; c < 512; c += 256) {
            int r = c >> 3, c8 = (c & 7)*8;
            *(uint4*)(Ks + r*QLD + c8) = *(const uint4*)(kbase + (size_t)r*DD + c8);
            *(uint4*)(Vs + r*QLD + c8) = *(const uint4*)(vbase + (size_t)r*DD + c8);
        }
    }
    __syncthreads();

    {
        wmma::fragment<wmma::accumulator,16,16,16,float> sc[4];
        #pragma unroll
        for (int n = 0; n < 4; n++) wmma::fill_fragment(sc[n], 0.f);
        #pragma unroll
        for (int k0 = 0; k0 < 64; k0 += 16) {
            wmma::fragment<wmma::matrix_a,16,16,16,__nv_bfloat16,wmma::row_major> af;
            wmma::load_matrix_sync(af, Qs + warp*16*QLD + k0, QLD);
            #pragma unroll
            for (int n = 0; n < 4; n++) {
                wmma::fragment<wmma::matrix_b,16,16,16,__nv_bfloat16,wmma::col_major> bf;
                wmma::load_matrix_sync(bf, Ks + n*16*QLD + k0, QLD);
                wmma::mma_sync(sc[n], af, bf, sc[n]);
            }
        }
        #pragma unroll
        for (int n = 0; n < 4; n++)
            wmma::store_matrix_sync(Ss + warp*16*SLD + n*16, sc[n], SLD, wmma::mem_row_major);
    }
    __syncthreads();

    {
        int row = tid >> 1, half = tid & 1;
        const float* srow = Ss + row*SLD + half*32;
        float e[32]; float s = 0.f;
        #pragma unroll
        for (int j = 0; j < 32; j++) { e[j] = __expf(srow[j]*0.125f); s += e[j]; }
        float tot = s + __shfl_xor_sync(0xffffffffu, s, 1);
        float inv = 1.f / tot;
        __nv_bfloat162* prow = (__nv_bfloat162*)(Ps + row*QLD + half*32);
        #pragma unroll
        for (int j = 0; j < 16; j++)
            prow[j] = __float22bfloat162_rn(make_float2(e[2*j]*inv, e[2*j+1]*inv));
    }
    __syncthreads();

    {
        wmma::fragment<wmma::accumulator,16,16,16,float> oc[4];
        #pragma unroll
        for (int n = 0; n < 4; n++) wmma::fill_fragment(oc[n], 0.f);
        #pragma unroll
        for (int k0 = 0; k0 < 64; k0 += 16) {
            wmma::fragment<wmma::matrix_a,16,16,16,__nv_bfloat16,wmma::row_major> af;
            wmma::load_matrix_sync(af, Ps + warp*16*QLD + k0, QLD);
            #pragma unroll
            for (int n = 0; n < 4; n++) {
                wmma::fragment<wmma::matrix_b,16,16,16,__nv_bfloat16,wmma::row_major> bf;
                wmma::load_matrix_sync(bf, Vs + k0*QLD + n*16, QLD);
                wmma::mma_sync(oc[n], af, bf, oc[n]);
            }
        }
        #pragma unroll
        for (int n = 0; n < 4; n++)
            wmma::store_matrix_sync(Ss + warp*16*SLD + n*16, oc[n], SLD, wmma::mem_row_major);

        int c = tid & 63, seg = tid >> 6;
        float part = 0.f;
        for (int r = seg*32; r < seg*32 + 32; r++)
            part += __bfloat162float(Ps[r*QLD + c]);
        atomicAdd(&colsum[c], part);
    }
    __syncthreads();

    {
        int row = tid >> 1, half = tid & 1;
        const float* orow = Ss + row*SLD + half*32;
        __nv_bfloat16* dst = g_attnout + (size_t)(b*TT + t0 + row)*DD + h*DH + half*32;
        #pragma unroll
        for (int jj = 0; jj < 4; jj++) {
            const float* s8 = orow + jj*8;
            __nv_bfloat162 p0 = __float22bfloat162_rn(make_float2(s8[0], s8[1]));
            __nv_bfloat162 p1 = __float22bfloat162_rn(make_float2(s8[2], s8[3]));
            __nv_bfloat162 p2 = __float22bfloat162_rn(make_float2(s8[4], s8[5]));
            __nv_bfloat162 p3 = __float22bfloat162_rn(make_float2(s8[6], s8[7]));
            uint4 pk;
            pk.x = *(unsigned*)&p0; pk.y = *(unsigned*)&p1;
            pk.z = *(unsigned*)&p2; pk.w = *(unsigned*)&p3;
            *(uint4*)(dst + jj*8) = pk;
        }
        if (tid < 64) atomicAdd(&g_attnsum[b*KSEL + tid], colsum[tid]);
    }
}

// ---------------- scatter mean attention ----------------
__global__ void scatter_kernel(float* __restrict__ dout) {
    int i = threadIdx.x;
    if (i < BB*KSEL) {
        int b = i >> 6;
        dout[BTD + b*NN + g_topk[i]] = g_attnsum[i] * (1.f / (HH*TT));
    }
}

// ---------------- launch (serial stream 0) ----------------
extern "C" void kernel_launch(void* const* d_in, const int* in_sizes, int n_in,
                              void* d_out, int out_size) {
    const float* h    = (const float*)d_in[0];
    const float* mem  = (const float*)d_in[1];
    const float* act  = (const float*)d_in[2];
    const float* ln_g = (const float*)d_in[3];
    const float* ln_b = (const float*)d_in[4];
    const float* fw   = (const float*)d_in[5];
    const float* fb   = (const float*)d_in[6];
    const float* qw   = (const float*)d_in[7];
    const float* qb   = (const float*)d_in[8];
    const float* kw   = (const float*)d_in[9];
    const float* kb   = (const float*)d_in[10];
    const float* vw   = (const float*)d_in[11];
    const float* vb   = (const float*)d_in[12];
    const float* ow   = (const float*)d_in[13];
    const float* ob   = (const float*)d_in[14];
    const float* awp  = (const float*)d_in[15];
    const float* glp  = (const float*)d_in[16];
    float* dout = (float*)d_out;

    __nv_bfloat16 *wq;
    cudaGetSymbolAddress((void**)&wq, g_wbf);
    __nv_bfloat16 *wk = wq + DD2, *wo = wq + 3*DD2;
    __nv_bfloat16 *hnorm, *attnout, *qbf, *kvbf;
    cudaGetSymbolAddress((void**)&hnorm, g_hnorm);
    cudaGetSymbolAddress((void**)&attnout, g_attnout);
    cudaGetSymbolAddress((void**)&qbf, g_qbf);
    cudaGetSymbolAddress((void**)&kvbf, g_kvbf);

    cudaFuncSetAttribute(gemm_bf16<0>, cudaFuncAttributeMaxDynamicSharedMemorySize, SMEM_GEMM);
    cudaFuncSetAttribute(gemm_bf16<1>, cudaFuncAttributeMaxDynamicSharedMemorySize, SMEM_GEMM);
    cudaFuncSetAttribute(gemm_bf16<2>, cudaFuncAttributeMaxDynamicSharedMemorySize, SMEM_GEMM);
    cudaFuncSetAttribute(attn_kernel, cudaFuncAttributeMaxDynamicSharedMemorySize, SMEM_ATTN);

    convw_zero_kernel<<<2048, 256>>>(qw, kw, vw, ow, dout);
    ln_kernel<<<BT, 256>>>(h, ln_g, ln_b);

    // q-gemm — profiled slot
    gemm_bf16<0><<<dim3(DD/BNG, BT/BMG), NTHR, SMEM_GEMM>>>(
        hnorm, wq, qb, nullptr, qbf, nullptr, nullptr, nullptr, BT, DD, DD);

    hsum_kernel<<<dim3(BB, 4, 32), 256>>>(h);
    focus_kernel<<<dim3(BB, 8), 256>>>(fw, fb, ln_g, ln_b);
    sel_kernel<<<NN/8, 256>>>(mem, act, awp);
    topk_kernel<<<BB, 1024>>>();

    // kv-gemm with fused gather (A read from fp32 memory via g_topk)
    gemm_bf16<2><<<dim3(DD/BNG, (BB*KSEL)/BMG, 2), NTHR, SMEM_GEMM>>>(
        nullptr, wk, kb, vb, kvbf, nullptr, nullptr, mem, BB*KSEL, DD, DD);

    attn_kernel<<<dim3(BB*HH, TT/128), 256, SMEM_ATTN>>>();

    gemm_bf16<1><<<dim3(DD/BNG, BT/BMG), NTHR, SMEM_GEMM>>>(
        attnout, wo, ob, nullptr, dout, h, glp, nullptr, BT, DD, DD);

    scatter_kernel<<<1, 512>>>(dout);
}

// round 15
// speedup vs baseline: 1.0920x; 1.0920x over previous
#include <cuda_runtime.h>
#include <cuda_bf16.h>
#include <mma.h>
#include <math.h>
#include <stdint.h>
#include <cstdint>

using namespace nvcuda;

// ---------------- problem constants ----------------
#define BB 8
#define TT 2048
#define DD 1024
#define NN 32768
#define KSEL 64
#define HH 16
#define DH 64
#define LN_EPS 1e-5f

#define BT (BB*TT)          // 16384
#define BTD (BB*TT*DD)      // 16777216
#define DD2 (DD*DD)         // 1048576

// ---------------- device scratch ----------------
__device__ __nv_bfloat16 g_hnorm[BTD];
__device__ float g_mu[BT];
__device__ float g_rstd[BT];
__device__ float g_hsumraw[BB*DD];
__device__ float g_fq[BB*DD];
__device__ float g_sel[BB*NN];
__device__ int   g_topk[BB*KSEL];
__device__ __nv_bfloat16 g_tkmem[BB*KSEL*DD];
__device__ __nv_bfloat16 g_kvbf[2*BB*KSEL*DD];  // k then v (bf16)
__device__ __nv_bfloat16 g_qbf[BTD];            // q bf16
__device__ __nv_bfloat16 g_attnout[BTD];
__device__ float g_attnsum[BB*KSEL];
__device__ __nv_bfloat16 g_wbf[4*DD2];          // qw, kw, vw, ow bf16

// ---------------- weight conversion + zeroing (fused) ----------------
__global__ void convw_zero_kernel(const float* __restrict__ qw, const float* __restrict__ kw,
                                  const float* __restrict__ vw, const float* __restrict__ ow,
                                  float* __restrict__ dout) {
    int g = blockIdx.x*256 + threadIdx.x;
    if (g < BB*NN) dout[BTD + g] = 0.f;
    if (g < BB*DD) { g_hsumraw[g] = 0.f; g_fq[g] = 0.f; }
    if (g < BB*KSEL) g_attnsum[g] = 0.f;
    for (int i = g; i < DD2; i += 2048*256) {
        g_wbf[i]         = __float2bfloat16(qw[i]);
        g_wbf[DD2 + i]   = __float2bfloat16(kw[i]);
        g_wbf[2*DD2 + i] = __float2bfloat16(vw[i]);
        g_wbf[3*DD2 + i] = __float2bfloat16(ow[i]);
    }
}

// ---------------- LayerNorm -> bf16 h_norm ----------------
__global__ __launch_bounds__(256) void ln_kernel(const float* __restrict__ h,
                                                 const float* __restrict__ lg,
                                                 const float* __restrict__ lb) {
    int row = blockIdx.x;
    int tid = threadIdx.x;
    const float4* x4 = (const float4*)(h + (size_t)row*DD);
    float4 v = x4[tid];
    float s  = v.x + v.y + v.z + v.w;
    float s2 = v.x*v.x + v.y*v.y + v.z*v.z + v.w*v.w;
    #pragma unroll
    for (int o = 16; o; o >>= 1) {
        s  += __shfl_xor_sync(0xffffffffu, s, o);
        s2 += __shfl_xor_sync(0xffffffffu, s2, o);
    }
    __shared__ float ws[8], ws2[8];
    __shared__ float smu, srstd;
    if ((tid & 31) == 0) { ws[tid>>5] = s; ws2[tid>>5] = s2; }
    __syncthreads();
    if (tid == 0) {
        float ts = 0.f, ts2 = 0.f;
        #pragma unroll
        for (int i = 0; i < 8; i++) { ts += ws[i]; ts2 += ws2[i]; }
        float mu = ts / DD;
        float var = ts2 / DD - mu*mu;
        float rstd = rsqrtf(var + LN_EPS);
        smu = mu; srstd = rstd;
        g_mu[row] = mu; g_rstd[row] = rstd;
    }
    __syncthreads();
    float mu = smu, rstd = srstd;
    const float4* g4 = (const float4*)lg;
    const float4* b4 = (const float4*)lb;
    float4 gg = g4[tid], bb = b4[tid];
    __nv_bfloat16* out = g_hnorm + (size_t)row*DD + tid*4;
    out[0] = __float2bfloat16((v.x - mu)*rstd*gg.x + bb.x);
    out[1] = __float2bfloat16((v.y - mu)*rstd*gg.y + bb.y);
    out[2] = __float2bfloat16((v.z - mu)*rstd*gg.z + bb.z);
    out[3] = __float2bfloat16((v.w - mu)*rstd*gg.w + bb.w);
}

// ---------------- column sums of normalized h (fp32 path), 8-way MLP ----------------
__global__ __launch_bounds__(256) void hsum_kernel(const float* __restrict__ h) {
    int b = blockIdx.x;
    int j = blockIdx.y*256 + threadIdx.x;
    int t0 = blockIdx.z*64;
    float a0=0.f,a1=0.f,a2=0.f,a3=0.f,a4=0.f,a5=0.f,a6=0.f,a7=0.f;
    for (int t = t0; t < t0 + 64; t += 8) {
        int r = b*TT + t;
        a0 += (h[(size_t)r*DD + j]     - g_mu[r])   * g_rstd[r];
        a1 += (h[(size_t)(r+1)*DD + j] - g_mu[r+1]) * g_rstd[r+1];
        a2 += (h[(size_t)(r+2)*DD + j] - g_mu[r+2]) * g_rstd[r+2];
        a3 += (h[(size_t)(r+3)*DD + j] - g_mu[r+3]) * g_rstd[r+3];
        a4 += (h[(size_t)(r+4)*DD + j] - g_mu[r+4]) * g_rstd[r+4];
        a5 += (h[(size_t)(r+5)*DD + j] - g_mu[r+5]) * g_rstd[r+5];
        a6 += (h[(size_t)(r+6)*DD + j] - g_mu[r+6]) * g_rstd[r+6];
        a7 += (h[(size_t)(r+7)*DD + j] - g_mu[r+7]) * g_rstd[r+7];
    }
    atomicAdd(&g_hsumraw[b*DD + j], ((a0+a1)+(a2+a3)) + ((a4+a5)+(a6+a7)));
}

// ---------------- focus_query (fp32), split over K-slices ----------------
__global__ __launch_bounds__(256) void focus_kernel(const float* __restrict__ fw,
                                                    const float* __restrict__ fb,
                                                    const float* __restrict__ lg,
                                                    const float* __restrict__ lb) {
    int b = blockIdx.x;
    int z = blockIdx.y;
    int tid = threadIdx.x;
    __shared__ float hs[128];
    for (int i = tid; i < 128; i += 256) {
        int gi = z*128 + i;
        hs[i] = (g_hsumraw[b*DD + gi] * (1.f/TT)) * lg[gi] + lb[gi];
    }
    __syncthreads();
    float acc[4] = {0.f, 0.f, 0.f, 0.f};
    for (int i = 0; i < 128; i++) {
        float hv = hs[i];
        const float* fr = fw + (size_t)(z*128 + i)*DD + tid;
        acc[0] += hv * fr[0];
        acc[1] += hv * fr[256];
        acc[2] += hv * fr[512];
        acc[3] += hv * fr[768];
    }
    #pragma unroll
    for (int k = 0; k < 4; k++) {
        float v = acc[k];
        if (z == 0) v += fb[tid + k*256];
        atomicAdd(&g_fq[b*DD + tid + k*256], v);
    }
}

// ---------------- selection = fq @ memory^T + aw * activations ----------------
__global__ __launch_bounds__(256) void sel_kernel(const float* __restrict__ mem,
                                                  const float* __restrict__ act,
                                                  const float* __restrict__ awp) {
    __shared__ float fqs[BB][DD];
    int tid = threadIdx.x;
    for (int i = tid; i < BB*DD; i += 256)
        fqs[i >> 10][i & 1023] = g_fq[i];
    __syncthreads();
    int warp = tid >> 5, lane = tid & 31;
    int n = blockIdx.x*8 + warp;
    float acc[BB];
    #pragma unroll
    for (int b = 0; b < BB; b++) acc[b] = 0.f;
    const float* mrow = mem + (size_t)n*DD;
    for (int i = lane; i < DD; i += 32) {
        float m = mrow[i];
        #pragma unroll
        for (int b = 0; b < BB; b++) acc[b] += m * fqs[b][i];
    }
    #pragma unroll
    for (int b = 0; b < BB; b++) {
        float a = acc[b];
        #pragma unroll
        for (int o = 16; o; o >>= 1) a += __shfl_xor_sync(0xffffffffu, a, o);
        if (lane == 0) g_sel[b*NN + n] = a + awp[0] * act[b*NN + n];
    }
}

// ---------------- exact top-64 via MSB-first radix select (parallel scans) ----------------
__device__ __forceinline__ unsigned fkey(float f) {
    unsigned u = __float_as_uint(f);
    return (u & 0x80000000u) ? ~u : (u | 0x80000000u);
}

__global__ __launch_bounds__(1024) void topk_kernel() {
    int b = blockIdx.x;
    int tid = threadIdx.x;
    __shared__ unsigned hist[256];
    __shared__ unsigned suf[256];
    __shared__ unsigned s_prefix;
    __shared__ int s_remaining;
    __shared__ unsigned s_gt, s_eq;
    __shared__ int eqidx[256];
    const float* sel = g_sel + b*NN;
    unsigned prefix = 0;
    int remaining = KSEL;
    for (int shift = 24; shift >= 0; shift -= 8) {
        if (tid < 256) hist[tid] = 0;
        __syncthreads();
        for (int i = tid; i < NN; i += 1024) {
            unsigned k = fkey(sel[i]);
            bool match = (shift == 24) || ((k >> (shift+8)) == (prefix >> (shift+8)));
            if (match) atomicAdd(&hist[(k >> shift) & 255], 1u);
        }
        __syncthreads();
        if (tid < 256) suf[tid] = hist[tid];
        __syncthreads();
        #pragma unroll
        for (int off = 1; off < 256; off <<= 1) {
            unsigned v = 0;
            if (tid < 256) {
                v = suf[tid];
                if (tid + off < 256) v += suf[tid + off];
            }
            __syncthreads();
            if (tid < 256) suf[tid] = v;
            __syncthreads();
        }
        if (tid < 256) {
            unsigned here = suf[tid];
            unsigned nxt = (tid == 255) ? 0u : suf[tid + 1];
            if (here >= (unsigned)remaining && nxt < (unsigned)remaining) {
                s_prefix = prefix | ((unsigned)tid << shift);
                s_remaining = remaining - (int)nxt;
            }
        }
        __syncthreads();
        prefix = s_prefix;
        remaining = s_remaining;
        __syncthreads();
    }
    if (tid == 0) { s_gt = 0; s_eq = 0; }
    __syncthreads();
    int* out = g_topk + b*KSEL;
    for (int i = tid; i < NN; i += 1024) {
        unsigned k = fkey(sel[i]);
        if (k > prefix) {
            out[atomicAdd(&s_gt, 1u)] = i;
        } else if (k == prefix) {
            unsigned p = atomicAdd(&s_eq, 1u);
            if (p < 256) eqidx[p] = i;
        }
    }
    __syncthreads();
    if (tid == 0) {
        int cnt = min((int)s_eq, 256);
        int base = (int)s_gt;
        for (int r = 0; r < remaining; r++) {
            int mi = 0;
            for (int i2 = 1; i2 < cnt; i2++)
                if (eqidx[i2] < eqidx[mi]) mi = i2;
            out[base + r] = eqidx[mi];
            eqidx[mi] = 0x7fffffff;
        }
    }
}

// ---------------- gather top-k memory rows -> bf16 ----------------
__global__ __launch_bounds__(256) void gather_kernel(const float* __restrict__ mem) {
    int bk = blockIdx.x;
    int idx = g_topk[bk];
    const float* src = mem + (size_t)idx*DD;
    __nv_bfloat16* dst = g_tkmem + (size_t)bk*DD;
    for (int i = threadIdx.x; i < DD; i += 256)
        dst[i] = __float2bfloat16(src[i]);
}

// ---------------- mma.sync helpers ----------------
__device__ __forceinline__ void ldsm_x4(uint32_t& r0, uint32_t& r1, uint32_t& r2, uint32_t& r3,
                                        uint32_t addr) {
    asm volatile("ldmatrix.sync.aligned.m8n8.x4.shared.b16 {%0,%1,%2,%3}, [%4];"
                 : "=r"(r0), "=r"(r1), "=r"(r2), "=r"(r3) : "r"(addr));
}
__device__ __forceinline__ void ldsm_x4_t(uint32_t& r0, uint32_t& r1, uint32_t& r2, uint32_t& r3,
                                          uint32_t addr) {
    asm volatile("ldmatrix.sync.aligned.m8n8.x4.trans.shared.b16 {%0,%1,%2,%3}, [%4];"
                 : "=r"(r0), "=r"(r1), "=r"(r2), "=r"(r3) : "r"(addr));
}
__device__ __forceinline__ void mma16816(float* c, const uint32_t* a, const uint32_t* b) {
    asm volatile("mma.sync.aligned.m16n8k16.row.col.f32.bf16.bf16.f32 "
                 "{%0,%1,%2,%3}, {%4,%5,%6,%7}, {%8,%9}, {%0,%1,%2,%3};"
                 : "+f"(c[0]), "+f"(c[1]), "+f"(c[2]), "+f"(c[3])
                 : "r"(a[0]), "r"(a[1]), "r"(a[2]), "r"(a[3]), "r"(b[0]), "r"(b[1]));
}

// ---------------- 3-stage cp.async hand-MMA GEMM ----------------
#define STG 3
#define BMG 128
#define BNG 128
#define BKG 64
#define NTHR 128
#define ALD (BKG+8)      // 72 bf16 (144B rows)
#define BLD (BNG+8)      // 136 bf16 (272B rows)
#define CLD 68           // epilogue fp32 staging stride (272B, conflict-free)
#define SMEM_GEMM (STG*(BMG*ALD + BKG*BLD)*2 + BNG*4)   // 108032

template<int EPI>
__global__ __launch_bounds__(NTHR, 2) void gemm_bf16(
    const __nv_bfloat16* __restrict__ A,
    const __nv_bfloat16* __restrict__ Bm,
    const float* __restrict__ bias,
    const float* __restrict__ bias2,
    void* __restrict__ Cout,
    const float* __restrict__ hres,
    const float* __restrict__ glp,
    int M, int N, int K)
{
    extern __shared__ char smraw[];
    __nv_bfloat16* As = (__nv_bfloat16*)smraw;               // 3 x 128x72
    __nv_bfloat16* Bs = As + STG*BMG*ALD;                    // 3 x 64x136
    float* biasT = (float*)(Bs + STG*BKG*BLD);               // 128

    int tid = threadIdx.x;
    int warp = tid >> 5, lane = tid & 31;
    int wm = warp >> 1;
    int wn = warp & 1;
    int rowBase = blockIdx.y * BMG;
    int colBase = blockIdx.x * BNG;

    const __nv_bfloat16* Bp = Bm;
    const float* bp = bias;
    size_t dstOff = 0;
    if (EPI == 2) {
        int z = blockIdx.z;
        Bp = Bm + (size_t)z * DD2;
        dstOff = (size_t)z * (BB*KSEL*DD);
        bp = z ? bias2 : bias;
    }

    if (tid < BNG) biasT[tid] = bp[colBase + tid];
    __syncthreads();

    float acc[4][8][4];
    {
        int cb = wn*64 + (lane & 3)*2;
        #pragma unroll
        for (int ni = 0; ni < 8; ni++) {
            float b0 = biasT[cb + ni*8];
            float b1 = biasT[cb + ni*8 + 1];
            #pragma unroll
            for (int mi = 0; mi < 4; mi++) {
                acc[mi][ni][0] = b0; acc[mi][ni][1] = b1;
                acc[mi][ni][2] = b0; acc[mi][ni][3] = b1;
            }
        }
    }

    auto load_stage = [&](int s, int k0) {
        #pragma unroll
        for (int c = 0; c < 8; c++) {
            int lin = tid + c*NTHR;
            int ar = lin >> 3, ac = (lin & 7)*8;
            unsigned da = (unsigned)__cvta_generic_to_shared(As + s*BMG*ALD + ar*ALD + ac);
            const void* ga = A + (size_t)(rowBase+ar)*K + k0 + ac;
            asm volatile("cp.async.cg.shared.global [%0], [%1], 16;\n" :: "r"(da), "l"(ga));
        }
        #pragma unroll
        for (int c = 0; c < 8; c++) {
            int lin = tid + c*NTHR;
            int br = lin >> 4, bc = (lin & 15)*8;
            unsigned db = (unsigned)__cvta_generic_to_shared(Bs + s*BKG*BLD + br*BLD + bc);
            const void* gb = Bp + (size_t)(k0+br)*N + colBase + bc;
            asm volatile("cp.async.cg.shared.global [%0], [%1], 16;\n" :: "r"(db), "l"(gb));
        }
        asm volatile("cp.async.commit_group;\n");
    };

    int NK = K / BKG;
    load_stage(0, 0);
    load_stage(1, BKG);

    int arow = lane & 15;
    int acol8 = (lane >> 4) * 8;

    for (int i = 0; i < NK; i++) {
        asm volatile("cp.async.wait_group %0;\n" :: "n"(STG-2));
        __syncthreads();
        if (i + STG - 1 < NK) load_stage((i + STG - 1) % STG, (i + STG - 1) * BKG);
        else asm volatile("cp.async.commit_group;\n");
        int buf = i % STG;
        const __nv_bfloat16* Ab = As + buf*BMG*ALD + (wm*64 + arow)*ALD + acol8;
        const __nv_bfloat16* Bb = Bs + buf*BKG*BLD + arow*BLD + wn*64 + acol8;
        #pragma unroll
        for (int kk = 0; kk < BKG; kk += 16) {
            uint32_t af[4][4];
            #pragma unroll
            for (int mi = 0; mi < 4; mi++) {
                uint32_t aaddr = (uint32_t)__cvta_generic_to_shared(Ab + mi*16*ALD + kk);
                ldsm_x4(af[mi][0], af[mi][1], af[mi][2], af[mi][3], aaddr);
            }
            uint32_t bf[4][4];
            #pragma unroll
            for (int nj = 0; nj < 4; nj++) {
                uint32_t baddr = (uint32_t)__cvta_generic_to_shared(Bb + kk*BLD + nj*16);
                ldsm_x4_t(bf[nj][0], bf[nj][1], bf[nj][2], bf[nj][3], baddr);
            }
            #pragma unroll
            for (int mi = 0; mi < 4; mi++)
                #pragma unroll
                for (int nj = 0; nj < 4; nj++) {
                    mma16816(acc[mi][nj*2],     af[mi], &bf[nj][0]);
                    mma16816(acc[mi][nj*2 + 1], af[mi], &bf[nj][2]);
                }
        }
    }

    asm volatile("cp.async.wait_group 0;\n");
    __syncthreads();
    float* Cs = (float*)smraw + warp*(64*CLD);
    {
        int r0 = lane >> 2;
        int c0 = (lane & 3)*2;
        #pragma unroll
        for (int mi = 0; mi < 4; mi++)
            #pragma unroll
            for (int ni = 0; ni < 8; ni++) {
                float* dst = Cs + (mi*16 + r0)*CLD + ni*8 + c0;
                *(float2*)dst            = make_float2(acc[mi][ni][0], acc[mi][ni][1]);
                *(float2*)(dst + 8*CLD)  = make_float2(acc[mi][ni][2], acc[mi][ni][3]);
            }
    }
    __syncwarp();

    int row0 = rowBase + wm*64;
    int col0 = colBase + wn*64;

    if (EPI == 1) {
        float* C = (float*)Cout;
        float gate = 1.f / (1.f + __expf(-glp[0]));
        for (int it = lane; it < 64*16; it += 32) {
            int r = it >> 4, c4 = (it & 15)*4;
            size_t gi = (size_t)(row0 + r)*N + col0 + c4;
            float4 hv = *(const float4*)(hres + gi);
            const float* src = Cs + r*CLD + c4;
            float4 o;
            o.x = hv.x + gate*src[0]; o.y = hv.y + gate*src[1];
            o.z = hv.z + gate*src[2]; o.w = hv.w + gate*src[3];
            *(float4*)(C + gi) = o;
        }
    } else {
        __nv_bfloat16* C = (__nv_bfloat16*)Cout + dstOff;
        for (int it = lane; it < 64*8; it += 32) {
            int r = it >> 3, c8 = (it & 7)*8;
            const float* src = Cs + r*CLD + c8;
            __nv_bfloat162 p0 = __float22bfloat162_rn(make_float2(src[0], src[1]));
            __nv_bfloat162 p1 = __float22bfloat162_rn(make_float2(src[2], src[3]));
            __nv_bfloat162 p2 = __float22bfloat162_rn(make_float2(src[4], src[5]));
            __nv_bfloat162 p3 = __float22bfloat162_rn(make_float2(src[6], src[7]));
            uint4 pk;
            pk.x = *(unsigned*)&p0; pk.y = *(unsigned*)&p1;
            pk.z = *(unsigned*)&p2; pk.w = *(unsigned*)&p3;
            *(uint4*)(C + (size_t)(row0 + r)*N + col0 + c8) = pk;
        }
    }
}

// ---------------- tensor-core attention (WMMA) ----------------
#define QLD 72
#define SLD 72
#define SMEM_ATTN ((128*QLD + 64*QLD + 64*QLD)*2 + 128*SLD*4 + 128*QLD*2 + 64*4)

__global__ __launch_bounds__(256) void attn_kernel() {
    extern __shared__ char smc[];
    __nv_bfloat16* Qs = (__nv_bfloat16*)smc;
    __nv_bfloat16* Ks = Qs + 128*QLD;
    __nv_bfloat16* Vs = Ks + 64*QLD;
    float* Ss = (float*)(Vs + 64*QLD);
    __nv_bfloat16* Ps = (__nv_bfloat16*)(Ss + 128*SLD);
    float* colsum = (float*)(Ps + 128*QLD);

    int bh = blockIdx.x;
    int b = bh >> 4;
    int h = bh & 15;
    int t0 = blockIdx.y * 128;
    int tid = threadIdx.x;
    int warp = tid >> 5;

    if (tid < 64) colsum[tid] = 0.f;
    {
        const __nv_bfloat16* qsrc = g_qbf + (size_t)(b*TT + t0)*DD + h*DH;
        #pragma unroll
        for (int c = tid; c < 1024; c += 256) {
            int r = c >> 3, c8 = (c & 7)*8;
            *(uint4*)(Qs + r*QLD + c8) = *(const uint4*)(qsrc + (size_t)r*DD + c8);
        }
        const __nv_bfloat16* kbase = g_kvbf + (size_t)b*KSEL*DD + h*DH;
        const __nv_bfloat16* vbase = kbase + (size_t)BB*KSEL*DD;
        for (int c = tid; c < 512; c += 256) {
            int r = c >> 3, c8 = (c & 7)*8;
            *(uint4*)(Ks + r*QLD + c8) = *(const uint4*)(kbase + (size_t)r*DD + c8);
            *(uint4*)(Vs + r*QLD + c8) = *(const uint4*)(vbase + (size_t)r*DD + c8);
        }
    }
    __syncthreads();

    {
        wmma::fragment<wmma::accumulator,16,16,16,float> sc[4];
        #pragma unroll
        for (int n = 0; n < 4; n++) wmma::fill_fragment(sc[n], 0.f);
        #pragma unroll
        for (int k0 = 0; k0 < 64; k0 += 16) {
            wmma::fragment<wmma::matrix_a,16,16,16,__nv_bfloat16,wmma::row_major> af;
            wmma::load_matrix_sync(af, Qs + warp*16*QLD + k0, QLD);
            #pragma unroll
            for (int n = 0; n < 4; n++) {
                wmma::fragment<wmma::matrix_b,16,16,16,__nv_bfloat16,wmma::col_major> bf;
                wmma::load_matrix_sync(bf, Ks + n*16*QLD + k0, QLD);
                wmma::mma_sync(sc[n], af, bf, sc[n]);
            }
        }
        #pragma unroll
        for (int n = 0; n < 4; n++)
            wmma::store_matrix_sync(Ss + warp*16*SLD + n*16, sc[n], SLD, wmma::mem_row_major);
    }
    __syncthreads();

    {
        int row = tid >> 1, half = tid & 1;
        const float* srow = Ss + row*SLD + half*32;
        float e[32]; float s = 0.f;
        #pragma unroll
        for (int j = 0; j < 32; j++) { e[j] = __expf(srow[j]*0.125f); s += e[j]; }
        float tot = s + __shfl_xor_sync(0xffffffffu, s, 1);
        float inv = 1.f / tot;
        __nv_bfloat162* prow = (__nv_bfloat162*)(Ps + row*QLD + half*32);
        #pragma unroll
        for (int j = 0; j < 16; j++)
            prow[j] = __float22bfloat162_rn(make_float2(e[2*j]*inv, e[2*j+1]*inv));
    }
    __syncthreads();

    {
        wmma::fragment<wmma::accumulator,16,16,16,float> oc[4];
        #pragma unroll
        for (int n = 0; n < 4; n++) wmma::fill_fragment(oc[n], 0.f);
        #pragma unroll
        for (int k0 = 0; k0 < 64; k0 += 16) {
            wmma::fragment<wmma::matrix_a,16,16,16,__nv_bfloat16,wmma::row_major> af;
            wmma::load_matrix_sync(af, Ps + warp*16*QLD + k0, QLD);
            #pragma unroll
            for (int n = 0; n < 4; n++) {
                wmma::fragment<wmma::matrix_b,16,16,16,__nv_bfloat16,wmma::row_major> bf;
                wmma::load_matrix_sync(bf, Vs + k0*QLD + n*16, QLD);
                wmma::mma_sync(oc[n], af, bf, oc[n]);
            }
        }
        #pragma unroll
        for (int n = 0; n < 4; n++)
            wmma::store_matrix_sync(Ss + warp*16*SLD + n*16, oc[n], SLD, wmma::mem_row_major);

        int c = tid & 63, seg = tid >> 6;
        float part = 0.f;
        for (int r = seg*32; r < seg*32 + 32; r++)
            part += __bfloat162float(Ps[r*QLD + c]);
        atomicAdd(&colsum[c], part);
    }
    __syncthreads();

    {
        int row = tid >> 1, half = tid & 1;
        const float* orow = Ss + row*SLD + half*32;
        __nv_bfloat16* dst = g_attnout + (size_t)(b*TT + t0 + row)*DD + h*DH + half*32;
        #pragma unroll
        for (int jj = 0; jj < 4; jj++) {
            const float* s8 = orow + jj*8;
            __nv_bfloat162 p0 = __float22bfloat162_rn(make_float2(s8[0], s8[1]));
            __nv_bfloat162 p1 = __float22bfloat162_rn(make_float2(s8[2], s8[3]));
            __nv_bfloat162 p2 = __float22bfloat162_rn(make_float2(s8[4], s8[5]));
            __nv_bfloat162 p3 = __float22bfloat162_rn(make_float2(s8[6], s8[7]));
            uint4 pk;
            pk.x = *(unsigned*)&p0; pk.y = *(unsigned*)&p1;
            pk.z = *(unsigned*)&p2; pk.w = *(unsigned*)&p3;
            *(uint4*)(dst + jj*8) = pk;
        }
        if (tid < 64) atomicAdd(&g_attnsum[b*KSEL + tid], colsum[tid]);
    }
}

// ---------------- scatter mean attention ----------------
__global__ void scatter_kernel(float* __restrict__ dout) {
    int i = threadIdx.x;
    if (i < BB*KSEL) {
        int b = i >> 6;
        dout[BTD + b*NN + g_topk[i]] = g_attnsum[i] * (1.f / (HH*TT));
    }
}

// ---------------- launch (serial stream 0) ----------------
extern "C" void kernel_launch(void* const* d_in, const int* in_sizes, int n_in,
                              void* d_out, int out_size) {
    const float* h    = (const float*)d_in[0];
    const float* mem  = (const float*)d_in[1];
    const float* act  = (const float*)d_in[2];
    const float* ln_g = (const float*)d_in[3];
    const float* ln_b = (const float*)d_in[4];
    const float* fw   = (const float*)d_in[5];
    const float* fb   = (const float*)d_in[6];
    const float* qw   = (const float*)d_in[7];
    const float* qb   = (const float*)d_in[8];
    const float* kw   = (const float*)d_in[9];
    const float* kb   = (const float*)d_in[10];
    const float* vw   = (const float*)d_in[11];
    const float* vb   = (const float*)d_in[12];
    const float* ow   = (const float*)d_in[13];
    const float* ob   = (const float*)d_in[14];
    const float* awp  = (const float*)d_in[15];
    const float* glp  = (const float*)d_in[16];
    float* dout = (float*)d_out;

    __nv_bfloat16 *wq;
    cudaGetSymbolAddress((void**)&wq, g_wbf);
    __nv_bfloat16 *wk = wq + DD2, *wo = wq + 3*DD2;
    __nv_bfloat16 *hnorm, *tkmem, *attnout, *qbf, *kvbf;
    cudaGetSymbolAddress((void**)&hnorm, g_hnorm);
    cudaGetSymbolAddress((void**)&tkmem, g_tkmem);
    cudaGetSymbolAddress((void**)&attnout, g_attnout);
    cudaGetSymbolAddress((void**)&qbf, g_qbf);
    cudaGetSymbolAddress((void**)&kvbf, g_kvbf);

    cudaFuncSetAttribute(gemm_bf16<0>, cudaFuncAttributeMaxDynamicSharedMemorySize, SMEM_GEMM);
    cudaFuncSetAttribute(gemm_bf16<1>, cudaFuncAttributeMaxDynamicSharedMemorySize, SMEM_GEMM);
    cudaFuncSetAttribute(gemm_bf16<2>, cudaFuncAttributeMaxDynamicSharedMemorySize, SMEM_GEMM);
    cudaFuncSetAttribute(attn_kernel, cudaFuncAttributeMaxDynamicSharedMemorySize, SMEM_ATTN);

    convw_zero_kernel<<<2048, 256>>>(qw, kw, vw, ow, dout);
    ln_kernel<<<BT, 256>>>(h, ln_g, ln_b);

    // q-gemm — profiled slot
    gemm_bf16<0><<<dim3(DD/BNG, BT/BMG), NTHR, SMEM_GEMM>>>(
        hnorm, wq, qb, nullptr, qbf, nullptr, nullptr, BT, DD, DD);

    hsum_kernel<<<dim3(BB, 4, 32), 256>>>(h);
    focus_kernel<<<dim3(BB, 8), 256>>>(fw, fb, ln_g, ln_b);
    sel_kernel<<<NN/8, 256>>>(mem, act, awp);
    topk_kernel<<<BB, 1024>>>();
    gather_kernel<<<BB*KSEL, 256>>>(mem);

    gemm_bf16<2><<<dim3(DD/BNG, (BB*KSEL)/BMG, 2), NTHR, SMEM_GEMM>>>(
        tkmem, wk, kb, vb, kvbf, nullptr, nullptr, BB*KSEL, DD, DD);

    attn_kernel<<<dim3(BB*HH, TT/128), 256, SMEM_ATTN>>>();

    gemm_bf16<1><<<dim3(DD/BNG, BT/BMG), NTHR, SMEM_GEMM>>>(
        attnout, wo, ob, nullptr, dout, h, glp, BT, DD, DD);

    scatter_kernel<<<1, 512>>>(dout);
}